// round 2
// baseline (speedup 1.0000x reference)
#include <cuda_runtime.h>

#define D_DIM 64
#define K_DIM 512
#define K_PAD 516          // pad so gather column reads don't 32-way conflict; keeps 16B alignment
#define TILE_ROWS 64
#define THREADS 256
#define NBLOCKS 148

typedef unsigned long long ull;

__device__ __forceinline__ ull pack_dup(float x) {
    ull r;
    asm("mov.b64 %0, {%1, %1};" : "=l"(r) : "f"(x));
    return r;
}

__device__ __forceinline__ void fma2(ull& d, ull a, ull b) {
    asm("fma.rn.f32x2 %0, %1, %2, %0;" : "+l"(d) : "l"(a), "l"(b));
}

__device__ __forceinline__ float2 unpack2(ull v) {
    float2 f;
    asm("mov.b64 {%0, %1}, %2;" : "=f"(f.x), "=f"(f.y) : "l"(v));
    return f;
}

// smem layout: sE[64][516] | se2[512] | sx[64][64]
#define SMEM_FLOATS (D_DIM * K_PAD + K_DIM + TILE_ROWS * D_DIM)

__global__ void __launch_bounds__(THREADS, 1)
vq_kernel(const float* __restrict__ x, const float* __restrict__ emb,
          float* __restrict__ out, int nrows, int ntiles)
{
    extern __shared__ float smem[];
    float* sE  = smem;                  // [64][516]
    float* se2 = sE + D_DIM * K_PAD;    // [512]
    float* sx  = se2 + K_DIM;           // [64][64]

    const int tid = threadIdx.x;

    // ---- Load codebook E[d][k] into padded smem (coalesced gmem float4 reads) ----
    for (int i = tid; i < D_DIM * K_DIM / 4; i += THREADS) {
        int d = (i * 4) / K_DIM;
        int k = (i * 4) % K_DIM;
        float4 v = *(const float4*)(emb + d * K_DIM + k);
        *(float4*)(sE + d * K_PAD + k) = v;
    }
    __syncthreads();

    // ---- ||e_k||^2 ----
    for (int k = tid; k < K_DIM; k += THREADS) {
        float s = 0.f;
        #pragma unroll 8
        for (int d = 0; d < D_DIM; d++) {
            float v = sE[d * K_PAD + k];
            s = fmaf(v, v, s);
        }
        se2[k] = s;
    }

    const int warp = tid >> 5;
    const int lane = tid & 31;
    const int r0 = warp * 8;            // 8 rows per warp, 8 warps -> 64-row tile

    for (int tile = blockIdx.x; tile < ntiles; tile += gridDim.x) {
        const int rowbase = tile * TILE_ROWS;

        __syncthreads();  // protect sx from readers of previous tile (also orders E/e2 on first iter)
        // ---- Load x tile (64 rows x 64 floats), coalesced float4 ----
        {
            const int total4 = TILE_ROWS * D_DIM / 4;
            const float* src = x + (size_t)rowbase * D_DIM;
            const int lim4 = (nrows - rowbase) * D_DIM / 4;  // guard partial last tile
            for (int i = tid; i < total4; i += THREADS) {
                float4 v = (i < lim4) ? *(const float4*)(src + i * 4)
                                      : make_float4(0.f, 0.f, 0.f, 0.f);
                *(float4*)(sx + i * 4) = v;
            }
        }
        __syncthreads();

        float minv[8];
        int   mini[8];
        #pragma unroll
        for (int r = 0; r < 8; r++) { minv[r] = 3.4e38f; mini[r] = 0; }

        // Two K-passes of 256 cols; lane owns cols {4*lane..+3} and {4*lane+128..+3}
        #pragma unroll
        for (int p = 0; p < 2; p++) {
            const int kbase = p * 256 + 4 * lane;

            ull acc[8][4];
            #pragma unroll
            for (int r = 0; r < 8; r++) {
                acc[r][0] = 0ull; acc[r][1] = 0ull; acc[r][2] = 0ull; acc[r][3] = 0ull;
            }

            #pragma unroll 4
            for (int d0 = 0; d0 < D_DIM; d0 += 4) {
                float4 xf[8];
                #pragma unroll
                for (int r = 0; r < 8; r++)
                    xf[r] = *(const float4*)(sx + (r0 + r) * D_DIM + d0);

                #pragma unroll
                for (int dd = 0; dd < 4; dd++) {
                    const float* eptr = sE + (d0 + dd) * K_PAD + kbase;
                    ulonglong2 e0 = *(const ulonglong2*)(eptr);         // cols kbase..+3
                    ulonglong2 e1 = *(const ulonglong2*)(eptr + 128);   // cols kbase+128..+3
                    #pragma unroll
                    for (int r = 0; r < 8; r++) {
                        float xs = (dd == 0) ? xf[r].x : (dd == 1) ? xf[r].y
                                 : (dd == 2) ? xf[r].z : xf[r].w;
                        ull xp = pack_dup(xs);
                        fma2(acc[r][0], xp, e0.x);
                        fma2(acc[r][1], xp, e0.y);
                        fma2(acc[r][2], xp, e1.x);
                        fma2(acc[r][3], xp, e1.y);
                    }
                }
            }

            // Scores + running argmin (k processed in strictly increasing order
            // within a lane -> strict '<' keeps first occurrence, matching jnp.argmin)
            #pragma unroll
            for (int r = 0; r < 8; r++) {
                #pragma unroll
                for (int q = 0; q < 4; q++) {
                    float2 dv = unpack2(acc[r][q]);
                    int k0 = kbase + (q >> 1) * 128 + (q & 1) * 2;
                    float s0 = fmaf(-2.f, dv.x, se2[k0]);
                    float s1 = fmaf(-2.f, dv.y, se2[k0 + 1]);
                    if (s0 < minv[r]) { minv[r] = s0; mini[r] = k0; }
                    if (s1 < minv[r]) { minv[r] = s1; mini[r] = k0 + 1; }
                }
            }
        }

        // ---- Warp argmin reduction (tie -> smaller k) + gather + write ----
        #pragma unroll
        for (int r = 0; r < 8; r++) {
            float v = minv[r];
            int   ki = mini[r];
            #pragma unroll
            for (int off = 16; off > 0; off >>= 1) {
                float ov = __shfl_down_sync(0xffffffffu, v, off);
                int   oi = __shfl_down_sync(0xffffffffu, ki, off);
                if (ov < v || (ov == v && oi < ki)) { v = ov; ki = oi; }
            }
            ki = __shfl_sync(0xffffffffu, ki, 0);

            int row = rowbase + r0 + r;
            if (row < nrows) {
                float2 o;
                o.x = sE[(2 * lane)     * K_PAD + ki];
                o.y = sE[(2 * lane + 1) * K_PAD + ki];
                *(float2*)(out + (size_t)row * D_DIM + 2 * lane) = o;
            }
        }
    }
}

extern "C" void kernel_launch(void* const* d_in, const int* in_sizes, int n_in,
                              void* d_out, int out_size)
{
    const float* x   = (const float*)d_in[0];   // inputs [B,H,W,D] fp32
    const float* emb = (const float*)d_in[1];   // embeddings [D,K] fp32
    float* out = (float*)d_out;

    int nrows  = in_sizes[0] / D_DIM;
    int ntiles = (nrows + TILE_ROWS - 1) / TILE_ROWS;

    size_t smem_bytes = SMEM_FLOATS * sizeof(float);   // 150528 B
    cudaFuncSetAttribute(vq_kernel, cudaFuncAttributeMaxDynamicSharedMemorySize,
                         (int)smem_bytes);

    int grid = NBLOCKS;
    if (grid > ntiles) grid = ntiles;
    vq_kernel<<<grid, THREADS, smem_bytes>>>(x, emb, out, nrows, ntiles);
}

// round 5
// speedup vs baseline: 1.0014x; 1.0014x over previous
#include <cuda_runtime.h>

#define D_DIM 64
#define K_DIM 512
#define K_PAD 516          // pad: keeps 16B alignment, breaks gather conflicts
#define TILE_ROWS 64
#define THREADS 512
#define NBLOCKS 148

typedef unsigned long long ull;

__device__ __forceinline__ ull pack_dup(float x) {
    ull r;
    asm("mov.b64 %0, {%1, %1};" : "=l"(r) : "f"(x));
    return r;
}

__device__ __forceinline__ void fma2(ull& d, ull a, ull b) {
    asm("fma.rn.f32x2 %0, %1, %2, %0;" : "+l"(d) : "l"(a), "l"(b));
}

__device__ __forceinline__ float2 unpack2(ull v) {
    float2 f;
    asm("mov.b64 {%0, %1}, %2;" : "=f"(f.x), "=f"(f.y) : "l"(v));
    return f;
}

// smem layout: sE[64][516] | se2[512] | sx[64][64]
#define SMEM_FLOATS (D_DIM * K_PAD + K_DIM + TILE_ROWS * D_DIM)

__global__ void __launch_bounds__(THREADS, 1)
vq_kernel(const float* __restrict__ x, const float* __restrict__ emb,
          float* __restrict__ out, int nrows, int ntiles)
{
    extern __shared__ float smem[];
    float* sE  = smem;                  // [64][516]
    float* se2 = sE + D_DIM * K_PAD;    // [512]
    float* sx  = se2 + K_DIM;           // [64][64]

    const int tid = threadIdx.x;

    // ---- Load codebook E[d][k] into padded smem (coalesced gmem float4 reads) ----
    for (int i = tid; i < D_DIM * K_DIM / 4; i += THREADS) {
        int d = (i * 4) / K_DIM;
        int k = (i * 4) % K_DIM;
        float4 v = *(const float4*)(emb + d * K_DIM + k);
        *(float4*)(sE + d * K_PAD + k) = v;
    }
    __syncthreads();

    // ---- ||e_k||^2 ----  (512 threads, one k each)
    if (tid < K_DIM) {
        int k = tid;
        float s = 0.f;
        #pragma unroll 8
        for (int d = 0; d < D_DIM; d++) {
            float v = sE[d * K_PAD + k];
            s = fmaf(v, v, s);
        }
        se2[k] = s;
    }

    const int warp = tid >> 5;
    const int lane = tid & 31;
    const int r0 = warp * 4;            // 4 rows per warp, 16 warps -> 64-row tile

    for (int tile = blockIdx.x; tile < ntiles; tile += gridDim.x) {
        const int rowbase = tile * TILE_ROWS;

        __syncthreads();  // protect sx from readers of previous tile (also orders E/e2 on first iter)
        // ---- Load x tile (64 rows x 64 floats), coalesced float4 ----
        {
            const int total4 = TILE_ROWS * D_DIM / 4;
            const float* src = x + (size_t)rowbase * D_DIM;
            const int lim4 = (nrows - rowbase) * D_DIM / 4;  // guard partial last tile
            for (int i = tid; i < total4; i += THREADS) {
                float4 v = (i < lim4) ? *(const float4*)(src + i * 4)
                                      : make_float4(0.f, 0.f, 0.f, 0.f);
                *(float4*)(sx + i * 4) = v;
            }
        }
        __syncthreads();

        float minv[4];
        int   mini[4];
        #pragma unroll
        for (int r = 0; r < 4; r++) { minv[r] = 3.4e38f; mini[r] = 0; }

        // Two K-passes of 256 cols; lane owns cols {4*lane..+3} and {4*lane+128..+3}
        #pragma unroll
        for (int p = 0; p < 2; p++) {
            const int kbase = p * 256 + 4 * lane;

            ull acc[4][4];
            #pragma unroll
            for (int r = 0; r < 4; r++) {
                acc[r][0] = 0ull; acc[r][1] = 0ull; acc[r][2] = 0ull; acc[r][3] = 0ull;
            }

            #pragma unroll 4
            for (int d0 = 0; d0 < D_DIM; d0 += 4) {
                float4 xf[4];
                #pragma unroll
                for (int r = 0; r < 4; r++)
                    xf[r] = *(const float4*)(sx + (r0 + r) * D_DIM + d0);  // broadcast

                #pragma unroll
                for (int dd = 0; dd < 4; dd++) {
                    const float* eptr = sE + (d0 + dd) * K_PAD + kbase;
                    ulonglong2 e0 = *(const ulonglong2*)(eptr);         // cols kbase..+3
                    ulonglong2 e1 = *(const ulonglong2*)(eptr + 128);   // cols kbase+128..+3
                    #pragma unroll
                    for (int r = 0; r < 4; r++) {
                        float xs = (dd == 0) ? xf[r].x : (dd == 1) ? xf[r].y
                                 : (dd == 2) ? xf[r].z : xf[r].w;
                        ull xp = pack_dup(xs);
                        fma2(acc[r][0], xp, e0.x);
                        fma2(acc[r][1], xp, e0.y);
                        fma2(acc[r][2], xp, e1.x);
                        fma2(acc[r][3], xp, e1.y);
                    }
                }
            }

            // se2 for this lane's 8 columns (row-independent -> hoisted out of r loop)
            float4 s2a = *(const float4*)(se2 + kbase);         // cols kbase..+3
            float4 s2b = *(const float4*)(se2 + kbase + 128);   // cols kbase+128..+3

            // Scores + running argmin (k processed in strictly increasing order
            // within a lane -> strict '<' keeps first occurrence, matching jnp.argmin)
            #pragma unroll
            for (int r = 0; r < 4; r++) {
                float2 d0v = unpack2(acc[r][0]);
                float2 d1v = unpack2(acc[r][1]);
                float2 d2v = unpack2(acc[r][2]);
                float2 d3v = unpack2(acc[r][3]);
                float s0 = fmaf(-2.f, d0v.x, s2a.x);
                float s1 = fmaf(-2.f, d0v.y, s2a.y);
                float s2 = fmaf(-2.f, d1v.x, s2a.z);
                float s3 = fmaf(-2.f, d1v.y, s2a.w);
                float s4 = fmaf(-2.f, d2v.x, s2b.x);
                float s5 = fmaf(-2.f, d2v.y, s2b.y);
                float s6 = fmaf(-2.f, d3v.x, s2b.z);
                float s7 = fmaf(-2.f, d3v.y, s2b.w);
                if (s0 < minv[r]) { minv[r] = s0; mini[r] = kbase;     }
                if (s1 < minv[r]) { minv[r] = s1; mini[r] = kbase + 1; }
                if (s2 < minv[r]) { minv[r] = s2; mini[r] = kbase + 2; }
                if (s3 < minv[r]) { minv[r] = s3; mini[r] = kbase + 3; }
                if (s4 < minv[r]) { minv[r] = s4; mini[r] = kbase + 128; }
                if (s5 < minv[r]) { minv[r] = s5; mini[r] = kbase + 129; }
                if (s6 < minv[r]) { minv[r] = s6; mini[r] = kbase + 130; }
                if (s7 < minv[r]) { minv[r] = s7; mini[r] = kbase + 131; }
            }
        }

        // ---- Warp argmin reduction (tie -> smaller k) + gather + write ----
        #pragma unroll
        for (int r = 0; r < 4; r++) {
            float v = minv[r];
            int   ki = mini[r];
            #pragma unroll
            for (int off = 16; off > 0; off >>= 1) {
                float ov = __shfl_down_sync(0xffffffffu, v, off);
                int   oi = __shfl_down_sync(0xffffffffu, ki, off);
                if (ov < v || (ov == v && oi < ki)) { v = ov; ki = oi; }
            }
            ki = __shfl_sync(0xffffffffu, ki, 0);

            int row = rowbase + r0 + r;
            if (row < nrows) {
                float2 o;
                o.x = sE[(2 * lane)     * K_PAD + ki];
                o.y = sE[(2 * lane + 1) * K_PAD + ki];
                *(float2*)(out + (size_t)row * D_DIM + 2 * lane) = o;
            }
        }
    }
}

extern "C" void kernel_launch(void* const* d_in, const int* in_sizes, int n_in,
                              void* d_out, int out_size)
{
    const float* x   = (const float*)d_in[0];   // inputs [B,H,W,D] fp32
    const float* emb = (const float*)d_in[1];   // embeddings [D,K] fp32
    float* out = (float*)d_out;

    int nrows  = in_sizes[0] / D_DIM;
    int ntiles = (nrows + TILE_ROWS - 1) / TILE_ROWS;

    size_t smem_bytes = SMEM_FLOATS * sizeof(float);   // 150528 B
    cudaFuncSetAttribute(vq_kernel, cudaFuncAttributeMaxDynamicSharedMemorySize,
                         (int)smem_bytes);

    int grid = NBLOCKS;
    if (grid > ntiles) grid = ntiles;
    vq_kernel<<<grid, THREADS, smem_bytes>>>(x, emb, out, nrows, ntiles);
}